// round 7
// baseline (speedup 1.0000x reference)
#include <cuda_runtime.h>
#include <cuda_bf16.h>
#include <cstdint>

#define NB 64
#define NN 512
#define ND 128
#define TB 128

// pre-normalized features, bf16 hi/lo planes
__device__ uint4 g_hi[(NB * NN * ND * 2) / 16];
__device__ uint4 g_lo[(NB * NN * ND * 2) / 16];

__device__ __forceinline__ uint32_t smem_u32(const void* p) {
    uint32_t a;
    asm("{ .reg .u64 t; cvta.to.shared.u64 t, %1; cvt.u32.u64 %0, t; }" : "=r"(a) : "l"(p));
    return a;
}
__device__ __forceinline__ float fsqrt_approx(float x) {
    float r;
    asm("sqrt.approx.f32 %0, %1;" : "=f"(r) : "f"(x));
    return r;
}

#define LDSM_X4(r, addr)                                                                  \
    asm volatile("ldmatrix.sync.aligned.m8n8.x4.shared.b16 {%0,%1,%2,%3}, [%4];"          \
                 : "=r"((r)[0]), "=r"((r)[1]), "=r"((r)[2]), "=r"((r)[3]) : "r"(addr))

#define CP_ASYNC16(sa, gp)                                                                \
    asm volatile("cp.async.cg.shared.global [%0], [%1], 16;" :: "r"(sa), "l"(gp) : "memory")
#define CP_COMMIT() asm volatile("cp.async.commit_group;" ::: "memory")
#define CP_WAIT(n)  asm volatile("cp.async.wait_group %0;" :: "n"(n) : "memory")

__device__ __forceinline__ void mma16816(float* c, uint32_t a0, uint32_t a1, uint32_t a2,
                                         uint32_t a3, uint32_t b0, uint32_t b1) {
    asm volatile("mma.sync.aligned.m16n8k16.row.col.f32.bf16.bf16.f32 "
                 "{%0,%1,%2,%3}, {%4,%5,%6,%7}, {%8,%9}, {%0,%1,%2,%3};"
                 : "+f"(c[0]), "+f"(c[1]), "+f"(c[2]), "+f"(c[3])
                 : "r"(a0), "r"(a1), "r"(a2), "r"(a3), "r"(b0), "r"(b1));
}

// smem layout: K-chunk = 32, row stride 80 B (conflict-free ldmatrix: 80 mod 128
// cycles all 8 16B-banks), double-buffered.
#define SMA32 80
#define PLANE32 10240         // 128 * 80
#define CHUNK32 40960         // 4 planes
#define OFF_AVT 0             // reuses operand buffers after MMA (67584 < 81920)
#define OFF_CI  81920         // 128 float2
#define OFF_CJ  82944
#define SMEM_TOTAL 83968
#define AVT_S 132

// ---------- prep: normalize rows, split to bf16 hi/lo ----------
__global__ void prep_kernel(const float* __restrict__ fea) {
    int row  = blockIdx.x * 8 + (threadIdx.x >> 5);
    int lane = threadIdx.x & 31;
    float4 v = reinterpret_cast<const float4*>(fea + (size_t)row * ND)[lane];
    float s = v.x * v.x + v.y * v.y + v.z * v.z + v.w * v.w;
    #pragma unroll
    for (int o = 16; o > 0; o >>= 1) s += __shfl_xor_sync(0xffffffffu, s, o);
    float rn = 1.0f / fmaxf(sqrtf(s), 1e-8f);
    float x0 = v.x * rn, x1 = v.y * rn, x2 = v.z * rn, x3 = v.w * rn;
    __nv_bfloat16 h0 = __float2bfloat16(x0), h1 = __float2bfloat16(x1);
    __nv_bfloat16 h2 = __float2bfloat16(x2), h3 = __float2bfloat16(x3);
    __nv_bfloat16 l0 = __float2bfloat16(x0 - __bfloat162float(h0));
    __nv_bfloat16 l1 = __float2bfloat16(x1 - __bfloat162float(h1));
    __nv_bfloat16 l2 = __float2bfloat16(x2 - __bfloat162float(h2));
    __nv_bfloat16 l3 = __float2bfloat16(x3 - __bfloat162float(h3));
    uint2 hv, lv;
    hv.x = (uint32_t)__bfloat16_as_ushort(h0) | ((uint32_t)__bfloat16_as_ushort(h1) << 16);
    hv.y = (uint32_t)__bfloat16_as_ushort(h2) | ((uint32_t)__bfloat16_as_ushort(h3) << 16);
    lv.x = (uint32_t)__bfloat16_as_ushort(l0) | ((uint32_t)__bfloat16_as_ushort(l1) << 16);
    lv.y = (uint32_t)__bfloat16_as_ushort(l2) | ((uint32_t)__bfloat16_as_ushort(l3) << 16);
    reinterpret_cast<uint2*>(g_hi)[(size_t)row * 32 + lane] = hv;
    reinterpret_cast<uint2*>(g_lo)[(size_t)row * 32 + lane] = lv;
}

// issue one K32 chunk's cp.async loads (4 per thread)
__device__ __forceinline__ void issue_chunk(uint32_t bufBase, int tid, int b,
                                            int iBase, int jBase, int kc) {
    #pragma unroll
    for (int it = 0; it < 4; it++) {
        int idx = tid + it * 512;
        int tile = idx >> 9;           // 512 16B-elements per plane
        int e = idx & 511;
        int row = e >> 2;
        int c8 = (e & 3) * 8;          // bf16 col within chunk: 0,8,16,24
        int rowsBase = (tile < 2) ? iBase : jBase;
        const uint4* src = (tile & 1) ? g_lo : g_hi;
        const uint4* gp = &src[((size_t)(b * NN + rowsBase + row) * ND + kc * 32 + c8) >> 3];
        uint32_t sa = bufBase + (uint32_t)(tile * PLANE32 + row * SMA32 + c8 * 2);
        CP_ASYNC16(sa, gp);
    }
    CP_COMMIT();
}

// ---------- main fused kernel: HMMA tile-pair, K32 double-buffered, 2 CTAs/SM ----------
__global__ __launch_bounds__(512, 2)
void adj_mma_kernel(const float* __restrict__ coord, float* __restrict__ out) {
    extern __shared__ char sm[];
    const uint32_t smb = smem_u32(sm);
    const int tid  = threadIdx.x;
    const int wid  = tid >> 5;
    const int lane = tid & 31;
    const int wy = wid >> 2;          // 0..3, m dim
    const int wx = wid & 3;           // 0..3, n dim

    const int blk = blockIdx.x;
    const int b = blk / 10;
    const int t = blk % 10;
    const unsigned char bi_t[10] = {0,0,0,0,1,1,1,2,2,3};
    const unsigned char bj_t[10] = {0,1,2,3,1,2,3,2,3,3};
    const int iBase = bi_t[t] * TB, jBase = bj_t[t] * TB;
    const bool diag = (iBase == jBase);

    // prologue: chunks 0,1 in flight
    issue_chunk(smb,           tid, b, iBase, jBase, 0);
    issue_chunk(smb + CHUNK32, tid, b, iBase, jBase, 1);

    // stage coords while loads stream
    {
        float2* ci2 = reinterpret_cast<float2*>(sm + OFF_CI);
        float2* cj2 = reinterpret_cast<float2*>(sm + OFF_CJ);
        if (tid < 128)
            ci2[tid] = reinterpret_cast<const float2*>(coord)[(size_t)b * NN + iBase + tid];
        else if (tid < 256)
            cj2[tid - 128] = reinterpret_cast<const float2*>(coord)[(size_t)b * NN + jBase + (tid - 128)];
    }

    float acc[2][4][4];
    #pragma unroll
    for (int mt = 0; mt < 2; mt++)
        #pragma unroll
        for (int nt = 0; nt < 4; nt++)
            #pragma unroll
            for (int q = 0; q < 4; q++) acc[mt][nt][q] = 0.0f;

    const uint32_t aOff = (uint32_t)((wy * 32 + lane) * SMA32);
    const uint32_t bOff = (uint32_t)(2 * PLANE32 + (wx * 32 + lane) * SMA32);

    #pragma unroll
    for (int kc = 0; kc < 4; kc++) {
        if (kc < 3) CP_WAIT(1); else CP_WAIT(0);
        __syncthreads();

        const uint32_t buf = smb + (uint32_t)((kc & 1) * CHUNK32);
        const uint32_t aH = buf + aOff;
        const uint32_t aL = aH + PLANE32;
        const uint32_t bH = buf + bOff;
        const uint32_t bL = bH + PLANE32;

        #pragma unroll
        for (int ks = 0; ks < 2; ks++) {
            const uint32_t co = (uint32_t)(ks * 32);
            // sequence products to cap live fragment registers (~24)
            uint32_t ah1[4], ah2[4], bh1[4], bh2[4];
            LDSM_X4(ah1, aH + co);
            LDSM_X4(ah2, aH + co + 16);
            LDSM_X4(bh1, bH + co);
            LDSM_X4(bh2, bH + co + 16);
            #pragma unroll
            for (int mt = 0; mt < 2; mt++)
                #pragma unroll
                for (int nt = 0; nt < 4; nt++)
                    mma16816(acc[mt][nt], ah1[mt*2], ah1[mt*2+1], ah2[mt*2], ah2[mt*2+1],
                             bh1[nt], bh2[nt]);
            {
                uint32_t bl1[4], bl2[4];
                LDSM_X4(bl1, bL + co);
                LDSM_X4(bl2, bL + co + 16);
                #pragma unroll
                for (int mt = 0; mt < 2; mt++)
                    #pragma unroll
                    for (int nt = 0; nt < 4; nt++)
                        mma16816(acc[mt][nt], ah1[mt*2], ah1[mt*2+1], ah2[mt*2], ah2[mt*2+1],
                                 bl1[nt], bl2[nt]);
            }
            {
                uint32_t al1[4], al2[4];
                LDSM_X4(al1, aL + co);
                LDSM_X4(al2, aL + co + 16);
                #pragma unroll
                for (int mt = 0; mt < 2; mt++)
                    #pragma unroll
                    for (int nt = 0; nt < 4; nt++)
                        mma16816(acc[mt][nt], al1[mt*2], al1[mt*2+1], al2[mt*2], al2[mt*2+1],
                                 bh1[nt], bh2[nt]);
            }
        }

        __syncthreads();                 // all warps done reading this buffer
        if (kc < 2) issue_chunk(buf, tid, b, iBase, jBase, kc + 2);
    }

    // epilogue: direct-tile stores from fragments + transposed staging for mirror
    {
        const float2* ci2 = reinterpret_cast<const float2*>(sm + OFF_CI);
        const float2* cj2 = reinterpret_cast<const float2*>(sm + OFF_CJ);
        float* avt = reinterpret_cast<float*>(sm + OFF_AVT);
        float* outA = out;
        float* outS = out + (size_t)NB * NN * NN;
        const size_t base = (size_t)b * NN * NN;
        const int g = lane >> 2, q = lane & 3;

        #pragma unroll
        for (int mt = 0; mt < 2; mt++) {
            #pragma unroll
            for (int nt = 0; nt < 4; nt++) {
                const float* c = acc[mt][nt];
                const int lj = wx * 32 + nt * 8 + q * 2;
                const float2 cj0 = cj2[lj], cj1 = cj2[lj + 1];
                #pragma unroll
                for (int h = 0; h < 2; h++) {
                    const int li = wy * 32 + mt * 16 + g + h * 8;
                    const float2 ci = ci2[li];
                    float dx0 = ci.x - cj0.x, dy0 = ci.y - cj0.y;
                    float dx1 = ci.x - cj1.x, dy1 = ci.y - cj1.y;
                    float d20 = dx0 * dx0 + dy0 * dy0;
                    float d21 = dx1 * dx1 + dy1 * dy1;
                    bool s0 = diag && (li == lj);
                    bool s1 = diag && (li == lj + 1);
                    float av0 = s0 ? 0.0f : c[h * 2 + 0] * __expf(-fsqrt_approx(d20));
                    float av1 = s1 ? 0.0f : c[h * 2 + 1] * __expf(-fsqrt_approx(d21));
                    float sv0 = (!s0 && d20 < 1.0f) ? 1.0f : 0.0f;
                    float sv1 = (!s1 && d21 < 1.0f) ? 1.0f : 0.0f;
                    size_t ro = base + (size_t)(iBase + li) * NN + jBase + lj;
                    *reinterpret_cast<float2*>(outA + ro) = make_float2(av0, av1);
                    *reinterpret_cast<float2*>(outS + ro) = make_float2(sv0, sv1);
                    if (!diag) {
                        avt[(size_t)lj * AVT_S + li]       = av0;
                        avt[(size_t)(lj + 1) * AVT_S + li] = av1;
                    }
                }
            }
        }
    }

    // mirror pass
    if (!diag) {
        __syncthreads();
        const float* avt = reinterpret_cast<const float*>(sm + OFF_AVT);
        const float2* cj2 = reinterpret_cast<const float2*>(sm + OFF_CJ);
        const float4* ci4 = reinterpret_cast<const float4*>(sm + OFF_CI);
        float* outA = out;
        float* outS = out + (size_t)NB * NN * NN;
        const size_t base = (size_t)b * NN * NN;

        #pragma unroll
        for (int it = 0; it < 8; it++) {
            const int r = wid * 8 + it;     // local j row
            float4 av4 = *reinterpret_cast<const float4*>(avt + (size_t)r * AVT_S + lane * 4);
            float2 cj = cj2[r];
            float4 p0 = ci4[lane * 2], p1 = ci4[lane * 2 + 1];
            float d0x = cj.x - p0.x, d0y = cj.y - p0.y;
            float d1x = cj.x - p0.z, d1y = cj.y - p0.w;
            float d2x = cj.x - p1.x, d2y = cj.y - p1.y;
            float d3x = cj.x - p1.z, d3y = cj.y - p1.w;
            float4 sv4;
            sv4.x = (d0x * d0x + d0y * d0y < 1.0f) ? 1.0f : 0.0f;
            sv4.y = (d1x * d1x + d1y * d1y < 1.0f) ? 1.0f : 0.0f;
            sv4.z = (d2x * d2x + d2y * d2y < 1.0f) ? 1.0f : 0.0f;
            sv4.w = (d3x * d3x + d3y * d3y < 1.0f) ? 1.0f : 0.0f;
            size_t ro = base + (size_t)(jBase + r) * NN + iBase + lane * 4;
            *reinterpret_cast<float4*>(outA + ro) = av4;
            *reinterpret_cast<float4*>(outS + ro) = sv4;
        }
    }
}

extern "C" void kernel_launch(void* const* d_in, const int* in_sizes, int n_in,
                              void* d_out, int out_size) {
    (void)in_sizes; (void)n_in; (void)out_size;
    const float* fea   = (const float*)d_in[0];
    const float* coord = (const float*)d_in[1];
    float* out = (float*)d_out;

    prep_kernel<<<NB * NN / 8, 256>>>(fea);

    cudaFuncSetAttribute(adj_mma_kernel, cudaFuncAttributeMaxDynamicSharedMemorySize, SMEM_TOTAL);
    adj_mma_kernel<<<NB * 10, 512, SMEM_TOTAL>>>(coord, out);
}

// round 8
// speedup vs baseline: 1.4161x; 1.4161x over previous
#include <cuda_runtime.h>
#include <cuda_bf16.h>
#include <cstdint>

#define NB 64
#define NN 512
#define ND 128
#define TB 128

// pre-normalized features, bf16 hi/lo planes
__device__ uint4 g_hi[(NB * NN * ND * 2) / 16];
__device__ uint4 g_lo[(NB * NN * ND * 2) / 16];

__device__ __forceinline__ uint32_t smem_u32(const void* p) {
    uint32_t a;
    asm("{ .reg .u64 t; cvta.to.shared.u64 t, %1; cvt.u32.u64 %0, t; }" : "=r"(a) : "l"(p));
    return a;
}
__device__ __forceinline__ float fsqrt_approx(float x) {
    float r;
    asm("sqrt.approx.f32 %0, %1;" : "=f"(r) : "f"(x));
    return r;
}

#define LDSM_X4(r, addr)                                                                  \
    asm volatile("ldmatrix.sync.aligned.m8n8.x4.shared.b16 {%0,%1,%2,%3}, [%4];"          \
                 : "=r"((r)[0]), "=r"((r)[1]), "=r"((r)[2]), "=r"((r)[3]) : "r"(addr))

#define CP_ASYNC16(sa, gp)                                                                \
    asm volatile("cp.async.cg.shared.global [%0], [%1], 16;" :: "r"(sa), "l"(gp) : "memory")
#define CP_COMMIT() asm volatile("cp.async.commit_group;" ::: "memory")
#define CP_WAIT(n)  asm volatile("cp.async.wait_group %0;" :: "n"(n) : "memory")

__device__ __forceinline__ void mma16816(float* c, uint32_t a0, uint32_t a1, uint32_t a2,
                                         uint32_t a3, uint32_t b0, uint32_t b1) {
    asm volatile("mma.sync.aligned.m16n8k16.row.col.f32.bf16.bf16.f32 "
                 "{%0,%1,%2,%3}, {%4,%5,%6,%7}, {%8,%9}, {%0,%1,%2,%3};"
                 : "+f"(c[0]), "+f"(c[1]), "+f"(c[2]), "+f"(c[3])
                 : "r"(a0), "r"(a1), "r"(a2), "r"(a3), "r"(b0), "r"(b1));
}

// smem: K-chunk 32, row stride 80 B (5*16B: coprime with 8 banks -> conflict-free
// ldmatrix). A planes 128 rows, B planes 64 rows. Double-buffered.
#define SMA32 80
#define APLANE 10240          // 128*80
#define BPLANE 5120           // 64*80
#define BOFF0  20480          // Bhi offset within chunk
#define CHUNK  30720          // Ahi,Alo,Bhi,Blo
#define OFF_CI 61440          // 128 float2
#define OFF_CJ 62464          // 64 float2
#define SMEM_TOTAL 62976
#define OFF_AVT 0             // 64*132*4 = 33792, reuses buffers after MMA
#define AVT_S 132

// ---------- prep: normalize rows, split to bf16 hi/lo ----------
__global__ void prep_kernel(const float* __restrict__ fea) {
    int row  = blockIdx.x * 8 + (threadIdx.x >> 5);
    int lane = threadIdx.x & 31;
    float4 v = reinterpret_cast<const float4*>(fea + (size_t)row * ND)[lane];
    float s = v.x * v.x + v.y * v.y + v.z * v.z + v.w * v.w;
    #pragma unroll
    for (int o = 16; o > 0; o >>= 1) s += __shfl_xor_sync(0xffffffffu, s, o);
    float rn = 1.0f / fmaxf(sqrtf(s), 1e-8f);
    float x0 = v.x * rn, x1 = v.y * rn, x2 = v.z * rn, x3 = v.w * rn;
    __nv_bfloat16 h0 = __float2bfloat16(x0), h1 = __float2bfloat16(x1);
    __nv_bfloat16 h2 = __float2bfloat16(x2), h3 = __float2bfloat16(x3);
    __nv_bfloat16 l0 = __float2bfloat16(x0 - __bfloat162float(h0));
    __nv_bfloat16 l1 = __float2bfloat16(x1 - __bfloat162float(h1));
    __nv_bfloat16 l2 = __float2bfloat16(x2 - __bfloat162float(h2));
    __nv_bfloat16 l3 = __float2bfloat16(x3 - __bfloat162float(h3));
    uint2 hv, lv;
    hv.x = (uint32_t)__bfloat16_as_ushort(h0) | ((uint32_t)__bfloat16_as_ushort(h1) << 16);
    hv.y = (uint32_t)__bfloat16_as_ushort(h2) | ((uint32_t)__bfloat16_as_ushort(h3) << 16);
    lv.x = (uint32_t)__bfloat16_as_ushort(l0) | ((uint32_t)__bfloat16_as_ushort(l1) << 16);
    lv.y = (uint32_t)__bfloat16_as_ushort(l2) | ((uint32_t)__bfloat16_as_ushort(l3) << 16);
    reinterpret_cast<uint2*>(g_hi)[(size_t)row * 32 + lane] = hv;
    reinterpret_cast<uint2*>(g_lo)[(size_t)row * 32 + lane] = lv;
}

// issue one K32 chunk (A: 128 rows hi+lo, B: 64 rows hi+lo) = 6 cp.async/thread
__device__ __forceinline__ void issue_chunk(uint32_t bufBase, int tid, int b,
                                            int iBase, int jBase64, int kc) {
    #pragma unroll
    for (int it = 0; it < 6; it++) {
        int idx = tid + it * 256;
        int plane, row, c8, grow;
        uint32_t soff;
        if (it < 4) {                  // A planes: 1024 uint4
            plane = idx >> 9;          // 0 = hi, 1 = lo
            int e = idx & 511;
            row = e >> 2;
            c8 = (e & 3) * 8;
            grow = iBase + row;
            soff = (uint32_t)(plane * APLANE + row * SMA32 + c8 * 2);
        } else {                       // B planes: 512 uint4
            int e = idx - 1024;
            plane = e >> 8;
            int e2 = e & 255;
            row = e2 >> 2;
            c8 = (e2 & 3) * 8;
            grow = jBase64 + row;
            soff = (uint32_t)(BOFF0 + plane * BPLANE + row * SMA32 + c8 * 2);
        }
        const uint4* src = plane ? g_lo : g_hi;
        const uint4* gp = &src[((size_t)(b * NN + grow) * ND + kc * 32 + c8) >> 3];
        CP_ASYNC16(bufBase + soff, gp);
    }
    CP_COMMIT();
}

// ---------- main: 128x64 half-tile jobs, 256 threads, 3 CTAs/SM ----------
__global__ __launch_bounds__(256, 3)
void adj_mma_kernel(const float* __restrict__ coord, float* __restrict__ out) {
    extern __shared__ char sm[];
    const uint32_t smb = smem_u32(sm);
    const int tid  = threadIdx.x;
    const int wid  = tid >> 5;
    const int lane = tid & 31;
    const int wy = wid & 3;           // 0..3, m dim (32 rows each)
    const int wx = wid >> 2;          // 0..1, n dim (32 cols each)

    const int blk = blockIdx.x;
    const int b = blk / 20;
    const int rem = blk % 20;
    const int t = rem >> 1;
    const int jHalf = rem & 1;
    const unsigned char bi_t[10] = {0,0,0,0,1,1,1,2,2,3};
    const unsigned char bj_t[10] = {0,1,2,3,1,2,3,2,3,3};
    const int iBase = bi_t[t] * TB;
    const int jBase = bj_t[t] * TB;
    const int jBase64 = jBase + jHalf * 64;
    const bool diag = (iBase == jBase);

    // prologue: chunks 0,1 in flight
    issue_chunk(smb,         tid, b, iBase, jBase64, 0);
    issue_chunk(smb + CHUNK, tid, b, iBase, jBase64, 1);

    // stage coords while loads stream
    {
        float2* ci2 = reinterpret_cast<float2*>(sm + OFF_CI);
        float2* cj2 = reinterpret_cast<float2*>(sm + OFF_CJ);
        if (tid < 128)
            ci2[tid] = reinterpret_cast<const float2*>(coord)[(size_t)b * NN + iBase + tid];
        else if (tid < 192)
            cj2[tid - 128] = reinterpret_cast<const float2*>(coord)[(size_t)b * NN + jBase64 + (tid - 128)];
    }

    float acc[2][4][4];
    #pragma unroll
    for (int mt = 0; mt < 2; mt++)
        #pragma unroll
        for (int nt = 0; nt < 4; nt++)
            #pragma unroll
            for (int q = 0; q < 4; q++) acc[mt][nt][q] = 0.0f;

    const uint32_t aOff = (uint32_t)((wy * 32 + lane) * SMA32);
    const uint32_t bOff = (uint32_t)(BOFF0 + (wx * 32 + lane) * SMA32);

    #pragma unroll
    for (int kc = 0; kc < 4; kc++) {
        if (kc < 3) CP_WAIT(1); else CP_WAIT(0);
        __syncthreads();

        const uint32_t buf = smb + (uint32_t)((kc & 1) * CHUNK);
        const uint32_t aH = buf + aOff;
        const uint32_t aL = aH + APLANE;
        const uint32_t bH = buf + bOff;
        const uint32_t bL = bH + BPLANE;

        #pragma unroll
        for (int ks = 0; ks < 2; ks++) {
            const uint32_t co = (uint32_t)(ks * 32);
            uint32_t ah1[4], ah2[4], bh1[4], bh2[4];
            LDSM_X4(ah1, aH + co);
            LDSM_X4(ah2, aH + co + 16);
            LDSM_X4(bh1, bH + co);
            LDSM_X4(bh2, bH + co + 16);
            #pragma unroll
            for (int mt = 0; mt < 2; mt++)
                #pragma unroll
                for (int nt = 0; nt < 4; nt++)
                    mma16816(acc[mt][nt], ah1[mt*2], ah1[mt*2+1], ah2[mt*2], ah2[mt*2+1],
                             bh1[nt], bh2[nt]);
            {
                uint32_t bl1[4], bl2[4];
                LDSM_X4(bl1, bL + co);
                LDSM_X4(bl2, bL + co + 16);
                #pragma unroll
                for (int mt = 0; mt < 2; mt++)
                    #pragma unroll
                    for (int nt = 0; nt < 4; nt++)
                        mma16816(acc[mt][nt], ah1[mt*2], ah1[mt*2+1], ah2[mt*2], ah2[mt*2+1],
                                 bl1[nt], bl2[nt]);
            }
            {
                uint32_t al1[4], al2[4];
                LDSM_X4(al1, aL + co);
                LDSM_X4(al2, aL + co + 16);
                #pragma unroll
                for (int mt = 0; mt < 2; mt++)
                    #pragma unroll
                    for (int nt = 0; nt < 4; nt++)
                        mma16816(acc[mt][nt], al1[mt*2], al1[mt*2+1], al2[mt*2], al2[mt*2+1],
                                 bh1[nt], bh2[nt]);
            }
        }

        __syncthreads();
        if (kc < 2) issue_chunk(buf, tid, b, iBase, jBase64, kc + 2);
    }

    // epilogue: direct-tile stores from fragments + transposed staging for mirror
    {
        const float2* ci2 = reinterpret_cast<const float2*>(sm + OFF_CI);
        const float2* cj2 = reinterpret_cast<const float2*>(sm + OFF_CJ);
        float* avt = reinterpret_cast<float*>(sm + OFF_AVT);
        float* outA = out;
        float* outS = out + (size_t)NB * NN * NN;
        const size_t base = (size_t)b * NN * NN;
        const int g = lane >> 2, q = lane & 3;

        #pragma unroll
        for (int mt = 0; mt < 2; mt++) {
            #pragma unroll
            for (int nt = 0; nt < 4; nt++) {
                const float* c = acc[mt][nt];
                const int lj = wx * 32 + nt * 8 + q * 2;      // 0..63
                const float2 cj0 = cj2[lj], cj1 = cj2[lj + 1];
                #pragma unroll
                for (int h = 0; h < 2; h++) {
                    const int li = wy * 32 + mt * 16 + g + h * 8;   // 0..127
                    const float2 ci = ci2[li];
                    float dx0 = ci.x - cj0.x, dy0 = ci.y - cj0.y;
                    float dx1 = ci.x - cj1.x, dy1 = ci.y - cj1.y;
                    float d20 = dx0 * dx0 + dy0 * dy0;
                    float d21 = dx1 * dx1 + dy1 * dy1;
                    bool s0 = diag && (li == jHalf * 64 + lj);
                    bool s1 = diag && (li == jHalf * 64 + lj + 1);
                    float av0 = s0 ? 0.0f : c[h * 2 + 0] * __expf(-fsqrt_approx(d20));
                    float av1 = s1 ? 0.0f : c[h * 2 + 1] * __expf(-fsqrt_approx(d21));
                    float sv0 = (!s0 && d20 < 1.0f) ? 1.0f : 0.0f;
                    float sv1 = (!s1 && d21 < 1.0f) ? 1.0f : 0.0f;
                    size_t ro = base + (size_t)(iBase + li) * NN + jBase64 + lj;
                    *reinterpret_cast<float2*>(outA + ro) = make_float2(av0, av1);
                    *reinterpret_cast<float2*>(outS + ro) = make_float2(sv0, sv1);
                    if (!diag) {
                        avt[(size_t)lj * AVT_S + li]       = av0;
                        avt[(size_t)(lj + 1) * AVT_S + li] = av1;
                    }
                }
            }
        }
    }

    // mirror pass: 64 rows (j) x 128 cols (i)
    if (!diag) {
        __syncthreads();
        const float* avt = reinterpret_cast<const float*>(sm + OFF_AVT);
        const float2* cj2 = reinterpret_cast<const float2*>(sm + OFF_CJ);
        const float4* ci4 = reinterpret_cast<const float4*>(sm + OFF_CI);
        float* outA = out;
        float* outS = out + (size_t)NB * NN * NN;
        const size_t base = (size_t)b * NN * NN;

        #pragma unroll
        for (int it = 0; it < 8; it++) {
            const int r = wid * 8 + it;     // local j row, 0..63
            float4 av4 = *reinterpret_cast<const float4*>(avt + (size_t)r * AVT_S + lane * 4);
            float2 cj = cj2[r];
            float4 p0 = ci4[lane * 2], p1 = ci4[lane * 2 + 1];
            float d0x = cj.x - p0.x, d0y = cj.y - p0.y;
            float d1x = cj.x - p0.z, d1y = cj.y - p0.w;
            float d2x = cj.x - p1.x, d2y = cj.y - p1.y;
            float d3x = cj.x - p1.z, d3y = cj.y - p1.w;
            float4 sv4;
            sv4.x = (d0x * d0x + d0y * d0y < 1.0f) ? 1.0f : 0.0f;
            sv4.y = (d1x * d1x + d1y * d1y < 1.0f) ? 1.0f : 0.0f;
            sv4.z = (d2x * d2x + d2y * d2y < 1.0f) ? 1.0f : 0.0f;
            sv4.w = (d3x * d3x + d3y * d3y < 1.0f) ? 1.0f : 0.0f;
            size_t ro = base + (size_t)(jBase64 + r) * NN + iBase + lane * 4;
            *reinterpret_cast<float4*>(outA + ro) = av4;
            *reinterpret_cast<float4*>(outS + ro) = sv4;
        }
    }
}

extern "C" void kernel_launch(void* const* d_in, const int* in_sizes, int n_in,
                              void* d_out, int out_size) {
    (void)in_sizes; (void)n_in; (void)out_size;
    const float* fea   = (const float*)d_in[0];
    const float* coord = (const float*)d_in[1];
    float* out = (float*)d_out;

    prep_kernel<<<NB * NN / 8, 256>>>(fea);

    cudaFuncSetAttribute(adj_mma_kernel, cudaFuncAttributeMaxDynamicSharedMemorySize, SMEM_TOTAL);
    adj_mma_kernel<<<NB * 20, 256, SMEM_TOTAL>>>(coord, out);
}